// round 14
// baseline (speedup 1.0000x reference)
#include <cuda_runtime.h>
#include <cstdint>

// NodeToWordsLayer: for each node (start,end) gather up to MAX_WORDS_PER_NODE=8
// rows of D=256 floats from bi_lstm, zero-filling invalid positions.
//
// Semantics (from reference):
//   word_count = (end == -1) ? 1 : end - start + 1
//   start_eff  = (start < 0) ? start + S : start
//   idx        = start_eff + pos            (pos in [0,8))
//   valid      = pos < word_count
//   idx_safe   = clip(idx, 0, S-1)
//   out[n,pos,:] = valid ? x[idx_safe,:] : 0
//
// ROUND-13 FIX: rel_err=1.18 diagnosed as nodes-dtype misparse. JAX with
// default x64-disabled silently downcasts jnp.int64 -> int32, so the nodes
// buffer is likely int32 pairs (8B/node), not int64 (16B/node). To be robust
// to BOTH, a tiny detection kernel scans odd int32 words of the nodes buffer:
// int64 layout -> those are sign-extension hi-words, always in {0,-1};
// int32 layout -> those are 'end' values, almost surely containing values
// outside {0,-1} within the first 2048 nodes. Flag lives in a __device__
// global; main kernel takes a grid-uniform branch.
//
// Perf layout (unchanged): 4 float4 (64B) per thread; lane=u&63, pos=(u>>6)&7,
// node=u>>9. One descriptor load + 4 gather LDG.128 (MLP=4) + 4 coalesced
// STG.128.CS per 64B. Branch-free FSEL zero-fill. Evict-first streaming
// stores keep the 10.24MB bi_lstm gather set L2-resident.
// DRAM ~= 410MB writes + ~10MB reads -> ~58us floor.

#define MAXW 8
#define D4   64   // 256 floats / 4

__device__ int g_nodes_is_i32;   // 1 if nodes buffer is int32 pairs

__global__ void detect_dtype_kernel(const int* __restrict__ w, int n_scan)
{
    __shared__ int sfound;
    if (threadIdx.x == 0) sfound = 0;
    __syncthreads();
    int f = 0;
    // odd int32 words: int64 layout -> hi-words in {0,-1}; int32 -> 'end's.
    for (int i = 1 + 2 * (int)threadIdx.x; i < n_scan; i += 2 * (int)blockDim.x) {
        int v = w[i];
        if (v != 0 && v != -1) f = 1;
    }
    if (f) atomicOr(&sfound, 1);
    __syncthreads();
    if (threadIdx.x == 0) g_nodes_is_i32 = sfound;
}

__global__ __launch_bounds__(512) void node_to_words_kernel(
    const void*  __restrict__ nodes_raw,   // [N] {start,end} pairs, i32 or i64
    const float4* __restrict__ x,          // [S, 64] float4 view of [S,256]
    float4*       __restrict__ out,        // [N, 8, 64] float4
    int N, int S)
{
    const int is32 = g_nodes_is_i32;       // grid-uniform runtime flag
    int total_quads = N * MAXW * (D4 / 4); // 4 float4 per thread-iteration
    int stride = gridDim.x * blockDim.x;

    for (int t = blockIdx.x * blockDim.x + threadIdx.x; t < total_quads;
         t += stride) {
        int u    = t << 2;                 // first float4 element index
        int lane = u & (D4 - 1);           // multiple of 4, in [0,60]
        int pos  = (u >> 6) & (MAXW - 1);
        int node = u >> 9;

        // Descriptor load: one LDG (8B or 16B), warp-broadcast.
        int s, e;
        if (is32) {
            int2 se = __ldg(&((const int2*)nodes_raw)[node]);
            s = se.x; e = se.y;
        } else {
            longlong2 se = __ldg(&((const longlong2*)nodes_raw)[node]);
            s = (int)se.x; e = (int)se.y;
        }

        int word_count = (e == -1) ? 1 : (e - s + 1);
        int start_eff  = (s < 0) ? (s + S) : s;
        int idx        = start_eff + pos;
        bool valid     = pos < word_count;

        idx = min(max(idx, 0), S - 1);

        // 32-bit gather offset (max 640000 float4) -> single IMAD.WIDE addr.
        int roff = idx * D4 + lane;
        const float4* row = &x[roff];
        // Always load (clamped addr is safe); 4 independent LDG.128 -> MLP=4.
        float4 v0 = __ldg(row);
        float4 v1 = __ldg(row + 1);
        float4 v2 = __ldg(row + 2);
        float4 v3 = __ldg(row + 3);

        // Exact-zero select (FSEL), not multiply-by-mask: correct even if
        // the gathered values were NaN/Inf, and identical issue cost.
        v0.x = valid ? v0.x : 0.f;  v0.y = valid ? v0.y : 0.f;
        v0.z = valid ? v0.z : 0.f;  v0.w = valid ? v0.w : 0.f;
        v1.x = valid ? v1.x : 0.f;  v1.y = valid ? v1.y : 0.f;
        v1.z = valid ? v1.z : 0.f;  v1.w = valid ? v1.w : 0.f;
        v2.x = valid ? v2.x : 0.f;  v2.y = valid ? v2.y : 0.f;
        v2.z = valid ? v2.z : 0.f;  v2.w = valid ? v2.w : 0.f;
        v3.x = valid ? v3.x : 0.f;  v3.y = valid ? v3.y : 0.f;
        v3.z = valid ? v3.z : 0.f;  v3.w = valid ? v3.w : 0.f;

        // Streaming stores: evict-first, keep bi_lstm resident in L2.
        __stcs(&out[u],     v0);
        __stcs(&out[u + 1], v1);
        __stcs(&out[u + 2], v2);
        __stcs(&out[u + 3], v3);
    }
}

extern "C" void kernel_launch(void* const* d_in, const int* in_sizes, int n_in,
                              void* d_out, int out_size)
{
    // Identify inputs by element count (robust to metadata ordering):
    // nodes has N*2 = 100K elements, bi_lstm has S*256 = 2.56M elements.
    int i_nodes = 0, i_x = 1;
    if (n_in >= 2 && in_sizes[0] > in_sizes[1]) { i_nodes = 1; i_x = 0; }

    const void*  nodes = d_in[i_nodes];
    const float4* x    = (const float4*)d_in[i_x];
    float4*      out   = (float4*)d_out;

    int N = in_sizes[i_nodes] / 2;     // node count (element count dtype-free)
    int S = in_sizes[i_x] / 256;       // sequence length

    // Dtype detection: scan first min(4096, 2N) int32 words (safe under
    // both layouts; int32 buffer holds 2N words, int64 holds 4N).
    int n_scan = 2 * N < 4096 ? 2 * N : 4096;
    detect_dtype_kernel<<<1, 256>>>((const int*)nodes, n_scan);

    int total_quads = N * MAXW * (D4 / 4);
    int threads = 512;
    int blocks  = (total_quads + threads - 1) / threads;  // exact cover

    node_to_words_kernel<<<blocks, threads>>>(nodes, x, out, N, S);
}

// round 17
// speedup vs baseline: 1.9713x; 1.9713x over previous
#include <cuda_runtime.h>
#include <cstdint>

// NodeToWordsLayer: gather up to 8 rows of 256 floats per node, zero-fill.
//
// ROUND-14 POST-MORTEM: 125us, DRAM=37%, L1=78.4% -> L1tex-wavefront bound.
// The old layout (4 CONSECUTIVE float4 per thread) made every individual
// LDG/STG warp-strided by 64B: 16 cache lines per warp-instruction instead
// of 4 -> 4x wavefront amplification through L1tex.
//
// FIX (still unmeasured due to infra timeouts; resubmitted frozen):
// warp-contiguous accesses. Thread handles u = base + k*blockDim + tid for
// k=0..3. Each LDG/STG covers 32 consecutive float4 (512B = 4 lines,
// minimal wavefronts). 32-aligned u keeps each warp-instruction inside ONE
// gathered row (lane 0..31 or 32..63) and ONE node descriptor (broadcast).
//
// Verified working (rel_err=0, DRAM reads ~0 beyond writes):
//  - dtype detection (nodes arrived as int32 pairs; JAX x64 downcast)
//  - __stcs evict-first stores protect the 10.24MB L2-resident bi_lstm
//  - branch-free FSEL zero-fill (exact 0, NaN/Inf-safe)
//
// Roofline: 410MB writes + ~10MB DRAM reads -> ~58us floor at ~7TB/s.

#define MAXW 8
#define D4   64    // 256 floats / 4
#define TPB  512
#define ITER 4     // float4 per thread, warp-strided

__device__ int g_nodes_is_i32;   // 1 if nodes buffer is int32 pairs

__global__ void detect_dtype_kernel(const int* __restrict__ w, int n_scan)
{
    __shared__ int sfound;
    if (threadIdx.x == 0) sfound = 0;
    __syncthreads();
    int f = 0;
    // odd int32 words: int64 layout -> hi-words in {0,-1}; int32 -> 'end's.
    for (int i = 1 + 2 * (int)threadIdx.x; i < n_scan; i += 2 * (int)blockDim.x) {
        int v = w[i];
        if (v != 0 && v != -1) f = 1;
    }
    if (f) atomicOr(&sfound, 1);
    __syncthreads();
    if (threadIdx.x == 0) g_nodes_is_i32 = sfound;
}

__global__ __launch_bounds__(TPB) void node_to_words_kernel(
    const void*   __restrict__ nodes_raw,  // [N] {start,end} pairs, i32 or i64
    const float4* __restrict__ x,          // [S, 64] float4 view of [S,256]
    float4*       __restrict__ out,        // [N, 8, 64] float4
    int N, int S)
{
    const int is32 = g_nodes_is_i32;       // grid-uniform runtime flag
    int total = N * MAXW * D4;             // total float4 elements (25.6M)
    int base  = blockIdx.x * (TPB * ITER) + threadIdx.x;

    // Decode all ITER elements and issue all loads first (front-batched,
    // MLP ~= 8 incl. descriptors), then select+store.
    int   uu[ITER];
    bool  vv[ITER];
    float4 d[ITER];

#pragma unroll
    for (int k = 0; k < ITER; k++) {
        int u = base + k * TPB;
        uu[k] = u;
        bool inb = (u < total);
        int usafe = inb ? u : 0;

        int lane = usafe & (D4 - 1);           // consecutive across warp
        int pos  = (usafe >> 6) & (MAXW - 1);
        int node = usafe >> 9;

        // One descriptor line per warp-instruction (broadcast, L1-hit).
        int s, e;
        if (is32) {
            int2 se = __ldg(&((const int2*)nodes_raw)[node]);
            s = se.x; e = se.y;
        } else {
            longlong2 se = __ldg(&((const longlong2*)nodes_raw)[node]);
            s = (int)se.x; e = (int)se.y;
        }

        int word_count = (e == -1) ? 1 : (e - s + 1);
        int start_eff  = (s < 0) ? (s + S) : s;
        int idx        = start_eff + pos;
        vv[k]          = (pos < word_count) && inb;

        idx = min(max(idx, 0), S - 1);

        // Warp-contiguous gather: 32 consecutive lanes -> 512B, 4 lines.
        d[k] = __ldg(&x[idx * D4 + lane]);
    }

#pragma unroll
    for (int k = 0; k < ITER; k++) {
        float4 v = d[k];
        bool val = vv[k];
        v.x = val ? v.x : 0.f;
        v.y = val ? v.y : 0.f;
        v.z = val ? v.z : 0.f;
        v.w = val ? v.w : 0.f;
        if (uu[k] < total) {
            // Warp-contiguous streaming store: 512B, 4 lines, evict-first.
            __stcs(&out[uu[k]], v);
        }
    }
}

extern "C" void kernel_launch(void* const* d_in, const int* in_sizes, int n_in,
                              void* d_out, int out_size)
{
    // Identify inputs by element count (robust to metadata ordering):
    // nodes has N*2 = 100K elements, bi_lstm has S*256 = 2.56M elements.
    int i_nodes = 0, i_x = 1;
    if (n_in >= 2 && in_sizes[0] > in_sizes[1]) { i_nodes = 1; i_x = 0; }

    const void*   nodes = d_in[i_nodes];
    const float4* x     = (const float4*)d_in[i_x];
    float4*       out   = (float4*)d_out;

    int N = in_sizes[i_nodes] / 2;     // node count (element count dtype-free)
    int S = in_sizes[i_x] / 256;       // sequence length

    // Dtype detection: scan first min(4096, 2N) int32 words (safe under
    // both layouts; int32 buffer holds 2N words, int64 holds 4N).
    int n_scan = 2 * N < 4096 ? 2 * N : 4096;
    detect_dtype_kernel<<<1, 256>>>((const int*)nodes, n_scan);

    int total  = N * MAXW * D4;                     // float4 elements
    int per_blk = TPB * ITER;
    int blocks  = (total + per_blk - 1) / per_blk;  // 12500 for N=50000

    node_to_words_kernel<<<blocks, TPB>>>(nodes, x, out, N, S);
}